// round 3
// baseline (speedup 1.0000x reference)
#include <cuda_runtime.h>
#include <math.h>

#define SEQ 4096
#define NH 8
#define HD 32
#define DM 256
#define IN_F 256

// ---------------- scratch (static device globals; no allocation) ----------------
__device__ float g_Q[NH * SEQ * HD];          // [h][n][d], pre-scaled by 1/sqrt(32)
__device__ float g_K[NH * SEQ * HD];          // [h][n][d]
__device__ float g_V[NH * SEQ * HD];          // [h][n][d]
__device__ float g_rowsum[NH * SEQ];          // softmax denominators (then inverted)
__device__ float g_ctx[SEQ * DM];             // unnormalized context [n][h*32+d]
__device__ float g_fc[SEQ * DM];              // pre-LN output
__device__ unsigned char g_mask[(size_t)SEQ * SEQ];
__device__ int g_mask_mode;                   // 0=u8, 1=i32, 2=f32

// ---------------- mask dtype detection + canonicalization ----------------
__global__ void detect_mask_kernel(const void* m) {
    const unsigned int* p = (const unsigned int*)m;
    int lane = threadIdx.x;
    int isint = 1, isfloat = 1;
    for (int i = lane; i < 256; i += 32) {
        unsigned int v = p[i];
        if (v > 1u) isint = 0;
        if (v != 0u && v != 0x3F800000u) isfloat = 0;
    }
    isint = __all_sync(0xFFFFFFFFu, isint);
    isfloat = __all_sync(0xFFFFFFFFu, isfloat);
    if (lane == 0) g_mask_mode = isint ? 1 : (isfloat ? 2 : 0);
}

__global__ void conv_mask_kernel(const void* m) {
    int mode = g_mask_mode;
    size_t idx = (size_t)blockIdx.x * blockDim.x + threadIdx.x;
    size_t stride = (size_t)gridDim.x * blockDim.x;
    size_t total = (size_t)SEQ * SEQ;
    if (mode == 1) {
        const int* p = (const int*)m;
        for (size_t i = idx; i < total; i += stride) g_mask[i] = (p[i] != 0);
    } else if (mode == 2) {
        const float* p = (const float*)m;
        for (size_t i = idx; i < total; i += stride) g_mask[i] = (p[i] != 0.0f);
    } else {
        const unsigned char* p = (const unsigned char*)m;
        for (size_t i = idx; i < total; i += stride) g_mask[i] = (p[i] != 0);
    }
}

// ---------------- input projections: Y = X @ W^T, split to [h][n][d] ----------------
__global__ __launch_bounds__(256) void proj_kernel(const float* __restrict__ X,
                                                   const float* __restrict__ W,
                                                   int which) {
    float* outp = (which == 0) ? g_Q : (which == 1) ? g_K : g_V;
    float scale = (which == 0) ? 0.17677669529663687f : 1.0f;  // 1/sqrt(32) into Q
    __shared__ float Xs[16][68];
    __shared__ float Ws[16][68];
    int bm = blockIdx.y * 64, bn = blockIdx.x * 64;
    int tid = threadIdx.x;
    int tx = (tid & 15) * 4, ty = (tid >> 4) * 4;
    float acc[4][4] = {};
    for (int k0 = 0; k0 < IN_F; k0 += 16) {
        for (int i = tid; i < 1024; i += 256) {
            int r = i >> 4, kk = i & 15;
            Xs[kk][r] = X[(size_t)(bm + r) * IN_F + k0 + kk];
            Ws[kk][r] = W[(size_t)(bn + r) * IN_F + k0 + kk];
        }
        __syncthreads();
#pragma unroll
        for (int kk = 0; kk < 16; kk++) {
            float xv[4], wv[4];
#pragma unroll
            for (int i = 0; i < 4; i++) xv[i] = Xs[kk][ty + i];
#pragma unroll
            for (int j = 0; j < 4; j++) wv[j] = Ws[kk][tx + j];
#pragma unroll
            for (int i = 0; i < 4; i++)
#pragma unroll
                for (int j = 0; j < 4; j++) acc[i][j] += xv[i] * wv[j];
        }
        __syncthreads();
    }
#pragma unroll
    for (int i = 0; i < 4; i++) {
        int m = bm + ty + i;
#pragma unroll
        for (int j = 0; j < 4; j++) {
            int o = bn + tx + j;
            outp[(size_t)(o >> 5) * (SEQ * HD) + (size_t)m * HD + (o & 31)] = acc[i][j] * scale;
        }
    }
}

// ---------------- fused attention: exp(scores)+mask -> attn(unnormalized), rowsum, ctx ----------------
__global__ __launch_bounds__(256) void attn_kernel(float* __restrict__ attn_out) {
    __shared__ __align__(16) float Qs[64][36];
    __shared__ __align__(16) float Ks[64][36];
    __shared__ float Vs[64][33];
    __shared__ __align__(16) float Es[64][64];
    int h = blockIdx.y;
    int qb = blockIdx.x * 64;
    int tid = threadIdx.x, warp = tid >> 5, lane = tid & 31;
    const float* Qg = g_Q + (size_t)h * SEQ * HD;
    const float* Kg = g_K + (size_t)h * SEQ * HD;
    const float* Vg = g_V + (size_t)h * SEQ * HD;
    for (int i = tid; i < 64 * 32; i += 256) {
        int r = i >> 5, c = i & 31;
        Qs[r][c] = Qg[(size_t)(qb + r) * HD + c];
    }
    __syncthreads();
    int r0 = warp * 8;
    float ctx[8] = {0, 0, 0, 0, 0, 0, 0, 0};
    float rsum[8] = {0, 0, 0, 0, 0, 0, 0, 0};
    for (int kc = 0; kc < SEQ; kc += 64) {
        for (int i = tid; i < 64 * 32; i += 256) {
            int r = i >> 5, c = i & 31;
            Ks[r][c] = Kg[(size_t)(kc + r) * HD + c];
            Vs[r][c] = Vg[(size_t)(kc + r) * HD + c];
        }
        __syncthreads();
        float acc0[8] = {0, 0, 0, 0, 0, 0, 0, 0};
        float acc1[8] = {0, 0, 0, 0, 0, 0, 0, 0};
#pragma unroll
        for (int d4 = 0; d4 < 8; d4++) {
            float4 ka = *(const float4*)&Ks[lane][d4 * 4];
            float4 kb = *(const float4*)&Ks[lane + 32][d4 * 4];
#pragma unroll
            for (int r = 0; r < 8; r++) {
                float4 q = *(const float4*)&Qs[r0 + r][d4 * 4];
                acc0[r] += q.x * ka.x + q.y * ka.y + q.z * ka.z + q.w * ka.w;
                acc1[r] += q.x * kb.x + q.y * kb.y + q.z * kb.z + q.w * kb.w;
            }
        }
#pragma unroll
        for (int r = 0; r < 8; r++) {
            int qg = qb + r0 + r;
            const unsigned char* mrow = g_mask + (size_t)qg * SEQ + kc;
            float e0 = mrow[lane] ? 0.0f : __expf(acc0[r]);
            float e1 = mrow[lane + 32] ? 0.0f : __expf(acc1[r]);
            Es[r0 + r][lane] = e0;
            Es[r0 + r][lane + 32] = e1;
            rsum[r] += e0 + e1;
        }
        __syncthreads();
        if (attn_out) {
            for (int i = tid; i < 64 * 16; i += 256) {
                int r = i >> 4, c4 = i & 15;
                *((float4*)(attn_out + ((size_t)h * SEQ + qb + r) * SEQ + kc) + c4) =
                    *(const float4*)&Es[r][c4 * 4];
            }
        }
#pragma unroll
        for (int k4 = 0; k4 < 16; k4++) {
            float v0 = Vs[k4 * 4 + 0][lane];
            float v1 = Vs[k4 * 4 + 1][lane];
            float v2 = Vs[k4 * 4 + 2][lane];
            float v3 = Vs[k4 * 4 + 3][lane];
#pragma unroll
            for (int r = 0; r < 8; r++) {
                float4 e = *(const float4*)&Es[r0 + r][k4 * 4];
                ctx[r] += e.x * v0 + e.y * v1 + e.z * v2 + e.w * v3;
            }
        }
        __syncthreads();
    }
#pragma unroll
    for (int r = 0; r < 8; r++) {
        float s = rsum[r];
#pragma unroll
        for (int o = 16; o; o >>= 1) s += __shfl_xor_sync(0xFFFFFFFFu, s, o);
        if (lane == 0) g_rowsum[h * SEQ + qb + r0 + r] = s;
        g_ctx[(size_t)(qb + r0 + r) * DM + h * HD + lane] = ctx[r];
    }
}

// ---------------- invert row sums ----------------
__global__ void rinv_kernel() {
    int i = blockIdx.x * 256 + threadIdx.x;
    if (i < NH * SEQ) g_rowsum[i] = 1.0f / g_rowsum[i];
}

// ---------------- normalize attn rows in place ----------------
__global__ __launch_bounds__(256) void norm_attn_kernel(float* __restrict__ attn) {
    int row = blockIdx.x;  // h*SEQ + q
    float inv = g_rowsum[row];
    float4* p = (float4*)(attn + (size_t)row * SEQ);
    for (int i = threadIdx.x; i < SEQ / 4; i += 256) {
        float4 v = p[i];
        v.x *= inv; v.y *= inv; v.z *= inv; v.w *= inv;
        p[i] = v;
    }
}

// ---------------- output projection: g_fc = (ctx * inv_sum) @ W_fc^T ----------------
__global__ __launch_bounds__(256) void fc_kernel(const float* __restrict__ W) {
    __shared__ float Xs[16][68];
    __shared__ float Ws[16][68];
    int bm = blockIdx.y * 64, bn = blockIdx.x * 64;
    int tid = threadIdx.x;
    int tx = (tid & 15) * 4, ty = (tid >> 4) * 4;
    float acc[4][4] = {};
    for (int k0 = 0; k0 < DM; k0 += 16) {
        for (int i = tid; i < 1024; i += 256) {
            int r = i >> 4, kk = i & 15;
            int c = k0 + kk;
            Xs[kk][r] = g_ctx[(size_t)(bm + r) * DM + c] * g_rowsum[(c >> 5) * SEQ + bm + r];
            Ws[kk][r] = W[(size_t)(bn + r) * DM + c];
        }
        __syncthreads();
#pragma unroll
        for (int kk = 0; kk < 16; kk++) {
            float xv[4], wv[4];
#pragma unroll
            for (int i = 0; i < 4; i++) xv[i] = Xs[kk][ty + i];
#pragma unroll
            for (int j = 0; j < 4; j++) wv[j] = Ws[kk][tx + j];
#pragma unroll
            for (int i = 0; i < 4; i++)
#pragma unroll
                for (int j = 0; j < 4; j++) acc[i][j] += xv[i] * wv[j];
        }
        __syncthreads();
    }
#pragma unroll
    for (int i = 0; i < 4; i++)
#pragma unroll
        for (int j = 0; j < 4; j++)
            g_fc[(size_t)(bm + ty + i) * DM + bn + tx + j] = acc[i][j];
}

// ---------------- LayerNorm ----------------
__global__ __launch_bounds__(256) void ln_kernel(const float* __restrict__ lnw,
                                                 const float* __restrict__ lnb,
                                                 float* __restrict__ out) {
    int n = blockIdx.x, t = threadIdx.x, lane = t & 31, w = t >> 5;
    __shared__ float red[8];
    float x = g_fc[(size_t)n * DM + t];
    float s = x;
#pragma unroll
    for (int o = 16; o; o >>= 1) s += __shfl_xor_sync(0xFFFFFFFFu, s, o);
    if (lane == 0) red[w] = s;
    __syncthreads();
    float mu = 0;
#pragma unroll
    for (int i = 0; i < 8; i++) mu += red[i];
    mu *= (1.0f / DM);
    __syncthreads();
    float d = x - mu;
    float s2 = d * d;
#pragma unroll
    for (int o = 16; o; o >>= 1) s2 += __shfl_xor_sync(0xFFFFFFFFu, s2, o);
    if (lane == 0) red[w] = s2;
    __syncthreads();
    float var = 0;
#pragma unroll
    for (int i = 0; i < 8; i++) var += red[i];
    var *= (1.0f / DM);
    out[(size_t)n * DM + t] = d * rsqrtf(var + 1e-5f) * lnw[t] + lnb[t];
}

// ---------------- launch ----------------
extern "C" void kernel_launch(void* const* d_in, const int* in_sizes, int n_in,
                              void* d_out, int out_size) {
    const float* iQ = (const float*)d_in[0];
    const float* iK = (const float*)d_in[1];
    const float* iV = (const float*)d_in[2];
    const void* mask = d_in[3];
    const float* WQ = (const float*)d_in[4];
    const float* WK = (const float*)d_in[5];
    const float* WV = (const float*)d_in[6];
    const float* Wfc = (const float*)d_in[7];
    const float* lnw = (const float*)d_in[8];
    const float* lnb = (const float*)d_in[9];
    float* out = (float*)d_out;

    long long attn_elems = (long long)NH * SEQ * SEQ;
    long long attn_off = (long long)out_size - attn_elems;
    float* attn_out = (attn_off >= 0) ? (out + attn_off) : nullptr;

    detect_mask_kernel<<<1, 32>>>(mask);
    conv_mask_kernel<<<4096, 256>>>(mask);
    proj_kernel<<<dim3(4, 64), 256>>>(iQ, WQ, 0);
    proj_kernel<<<dim3(4, 64), 256>>>(iK, WK, 1);
    proj_kernel<<<dim3(4, 64), 256>>>(iV, WV, 2);
    attn_kernel<<<dim3(64, 8), 256>>>(attn_out);
    rinv_kernel<<<(NH * SEQ + 255) / 256, 256>>>();
    if (attn_out) norm_attn_kernel<<<NH * SEQ, 256>>>(attn_out);
    fc_kernel<<<dim3(4, 64), 256>>>(Wfc);
    ln_kernel<<<SEQ, 256>>>(lnw, lnb, out);
}

// round 6
// speedup vs baseline: 2.0943x; 2.0943x over previous
#include <cuda_runtime.h>
#include <cuda_bf16.h>
#include <math.h>

#define SEQ 4096
#define NH 8
#define HD 32
#define DM 256
#define IN_F 256

typedef unsigned int u32;

// ---------------- scratch (static device globals; no allocation) ----------------
__device__ __nv_bfloat16 g_Qh[NH * SEQ * HD];  // bf16 hi part, Q pre-scaled by 1/sqrt(32)
__device__ __nv_bfloat16 g_Ql[NH * SEQ * HD];  // bf16 residual
__device__ __nv_bfloat16 g_Kh[NH * SEQ * HD];
__device__ __nv_bfloat16 g_Kl[NH * SEQ * HD];
__device__ __nv_bfloat16 g_Vh[NH * SEQ * HD];
__device__ __nv_bfloat16 g_Vl[NH * SEQ * HD];
__device__ float g_rowsum[NH * SEQ];
__device__ float g_ctx[SEQ * DM];
__device__ float g_fc[SEQ * DM];
__device__ unsigned char g_mask[(size_t)SEQ * SEQ];
__device__ int g_mask_mode;

// ---------------- mask dtype detection + canonicalization ----------------
__global__ void detect_mask_kernel(const void* m) {
    const unsigned int* p = (const unsigned int*)m;
    int lane = threadIdx.x;
    int isint = 1, isfloat = 1;
    for (int i = lane; i < 256; i += 32) {
        unsigned int v = p[i];
        if (v > 1u) isint = 0;
        if (v != 0u && v != 0x3F800000u) isfloat = 0;
    }
    isint = __all_sync(0xFFFFFFFFu, isint);
    isfloat = __all_sync(0xFFFFFFFFu, isfloat);
    if (lane == 0) g_mask_mode = isint ? 1 : (isfloat ? 2 : 0);
}

__global__ void conv_mask_kernel(const void* m) {
    int mode = g_mask_mode;
    size_t idx = (size_t)blockIdx.x * blockDim.x + threadIdx.x;
    size_t stride = (size_t)gridDim.x * blockDim.x;
    size_t total = (size_t)SEQ * SEQ;
    if (mode == 1) {
        const int* p = (const int*)m;
        for (size_t i = idx; i < total; i += stride) g_mask[i] = (p[i] != 0);
    } else if (mode == 2) {
        const float* p = (const float*)m;
        for (size_t i = idx; i < total; i += stride) g_mask[i] = (p[i] != 0.0f);
    } else {
        const unsigned char* p = (const unsigned char*)m;
        for (size_t i = idx; i < total; i += stride) g_mask[i] = (p[i] != 0);
    }
}

// ---------------- input projections: Y = X @ W^T -> bf16 hi/lo, split heads ----------------
// one merged launch: blockIdx.z = 0(Q) 1(K) 2(V)
__global__ __launch_bounds__(256) void proj_kernel(const float* __restrict__ XQ,
                                                   const float* __restrict__ XK,
                                                   const float* __restrict__ XV,
                                                   const float* __restrict__ WQ,
                                                   const float* __restrict__ WK,
                                                   const float* __restrict__ WV) {
    int which = blockIdx.z;
    const float* X = (which == 0) ? XQ : (which == 1) ? XK : XV;
    const float* W = (which == 0) ? WQ : (which == 1) ? WK : WV;
    __nv_bfloat16* oh = (which == 0) ? g_Qh : (which == 1) ? g_Kh : g_Vh;
    __nv_bfloat16* ol = (which == 0) ? g_Ql : (which == 1) ? g_Kl : g_Vl;
    float scale = (which == 0) ? 0.17677669529663687f : 1.0f;  // 1/sqrt(32) into Q
    __shared__ float Xs[16][68];
    __shared__ float Ws[16][68];
    int bm = blockIdx.y * 64, bn = blockIdx.x * 64;
    int tid = threadIdx.x;
    int tx = (tid & 15) * 4, ty = (tid >> 4) * 4;
    float acc[4][4] = {};
    for (int k0 = 0; k0 < IN_F; k0 += 16) {
        for (int i = tid; i < 1024; i += 256) {
            int r = i >> 4, kk = i & 15;
            Xs[kk][r] = X[(size_t)(bm + r) * IN_F + k0 + kk];
            Ws[kk][r] = W[(size_t)(bn + r) * IN_F + k0 + kk];
        }
        __syncthreads();
#pragma unroll
        for (int kk = 0; kk < 16; kk++) {
            float xv[4], wv[4];
#pragma unroll
            for (int i = 0; i < 4; i++) xv[i] = Xs[kk][ty + i];
#pragma unroll
            for (int j = 0; j < 4; j++) wv[j] = Ws[kk][tx + j];
#pragma unroll
            for (int i = 0; i < 4; i++)
#pragma unroll
                for (int j = 0; j < 4; j++) acc[i][j] += xv[i] * wv[j];
        }
        __syncthreads();
    }
#pragma unroll
    for (int i = 0; i < 4; i++) {
        int m = bm + ty + i;
#pragma unroll
        for (int j = 0; j < 4; j++) {
            int o = bn + tx + j;
            float v = acc[i][j] * scale;
            __nv_bfloat16 hi = __float2bfloat16_rn(v);
            float lo = v - __bfloat162float(hi);
            size_t dst = (size_t)(o >> 5) * (SEQ * HD) + (size_t)m * HD + (o & 31);
            oh[dst] = hi;
            ol[dst] = __float2bfloat16_rn(lo);
        }
    }
}

// ---------------- tensor-core attention ----------------
#define QSTR 40  // bf16 row stride for Q/K/V smem tiles
#define ESTR 72  // float row stride for Es
#define ATTN_SMEM (128 * QSTR * 2 * 2 + 64 * QSTR * 2 * 4 + 128 * ESTR * 4)

__device__ __forceinline__ u32 s2u(const void* p) { return (u32)__cvta_generic_to_shared(p); }

__device__ __forceinline__ void ldsm_x4(u32& r0, u32& r1, u32& r2, u32& r3, u32 addr) {
    asm volatile("ldmatrix.sync.aligned.m8n8.x4.shared.b16 {%0,%1,%2,%3}, [%4];"
                 : "=r"(r0), "=r"(r1), "=r"(r2), "=r"(r3) : "r"(addr));
}
__device__ __forceinline__ void ldsm_x4t(u32& r0, u32& r1, u32& r2, u32& r3, u32 addr) {
    asm volatile("ldmatrix.sync.aligned.m8n8.x4.trans.shared.b16 {%0,%1,%2,%3}, [%4];"
                 : "=r"(r0), "=r"(r1), "=r"(r2), "=r"(r3) : "r"(addr));
}
__device__ __forceinline__ void mma_bf16(float* c, const u32* a, u32 b0, u32 b1) {
    asm volatile(
        "mma.sync.aligned.m16n8k16.row.col.f32.bf16.bf16.f32 "
        "{%0,%1,%2,%3}, {%4,%5,%6,%7}, {%8,%9}, {%0,%1,%2,%3};"
        : "+f"(c[0]), "+f"(c[1]), "+f"(c[2]), "+f"(c[3])
        : "r"(a[0]), "r"(a[1]), "r"(a[2]), "r"(a[3]), "r"(b0), "r"(b1));
}
// pack two floats -> bf16x2 (first arg in bits[15:0], second in bits[31:16])
__device__ __forceinline__ u32 bpack(float lo, float hi) {
    u32 r;
    asm("cvt.rn.bf16x2.f32 %0, %1, %2;" : "=r"(r) : "f"(hi), "f"(lo));
    return r;
}

__global__ __launch_bounds__(256, 2) void attn_kernel(float* __restrict__ attn_out) {
    extern __shared__ char smem_raw[];
    __nv_bfloat16* sQh = (__nv_bfloat16*)smem_raw;
    __nv_bfloat16* sQl = sQh + 128 * QSTR;
    __nv_bfloat16* sKh = sQl + 128 * QSTR;
    __nv_bfloat16* sKl = sKh + 64 * QSTR;
    __nv_bfloat16* sVh = sKl + 64 * QSTR;
    __nv_bfloat16* sVl = sVh + 64 * QSTR;
    float* sEs = (float*)(sVl + 64 * QSTR);

    int h = blockIdx.y;
    int qb = blockIdx.x * 128;
    int tid = threadIdx.x, w = tid >> 5, lane = tid & 31;
    int g = lane >> 2, tig = lane & 3;

    // load Q tile (128x32 hi/lo) into smem
    {
        const uint4* srch = (const uint4*)(g_Qh + ((size_t)h * SEQ + qb) * HD);
        const uint4* srcl = (const uint4*)(g_Ql + ((size_t)h * SEQ + qb) * HD);
        for (int i = tid; i < 128 * 4; i += 256) {
            int r = i >> 2, c = i & 3;
            *(uint4*)(sQh + r * QSTR + c * 8) = srch[r * 4 + c];
            *(uint4*)(sQl + r * QSTR + c * 8) = srcl[r * 4 + c];
        }
    }
    __syncthreads();

    // Q fragments (held in registers for the whole kernel)
    u32 qa_h[2][4], qa_l[2][4];
    {
        int row = w * 16 + (lane & 15);
        int colb = ((lane >> 4) & 1) * 8;
#pragma unroll
        for (int kc = 0; kc < 2; kc++) {
            ldsm_x4(qa_h[kc][0], qa_h[kc][1], qa_h[kc][2], qa_h[kc][3],
                    s2u(&sQh[row * QSTR + kc * 16 + colb]));
            ldsm_x4(qa_l[kc][0], qa_l[kc][1], qa_l[kc][2], qa_l[kc][3],
                    s2u(&sQl[row * QSTR + kc * 16 + colb]));
        }
    }

    const __nv_bfloat16* Khp = g_Kh + (size_t)h * SEQ * HD;
    const __nv_bfloat16* Klp = g_Kl + (size_t)h * SEQ * HD;
    const __nv_bfloat16* Vhp = g_Vh + (size_t)h * SEQ * HD;
    const __nv_bfloat16* Vlp = g_Vl + (size_t)h * SEQ * HD;

    float rs0 = 0.0f, rs1 = 0.0f;
    float oc[4][4] = {};  // context accumulators [d8-tile][frag]
    int q0 = qb + w * 16 + g;
    const unsigned char* mbase0 = g_mask + (size_t)q0 * SEQ;
    const unsigned char* mbase1 = mbase0 + (size_t)8 * SEQ;

    for (int kc0 = 0; kc0 < SEQ; kc0 += 64) {
        // cooperative load K/V hi/lo tiles (64x32 each)
        {
            int i = tid;  // exactly 256 = 64*4 chunks
            int r = i >> 2, c = i & 3;
            size_t goff = (size_t)(kc0 + r) * HD + c * 8;
            *(uint4*)(sKh + r * QSTR + c * 8) = *(const uint4*)(Khp + goff);
            *(uint4*)(sKl + r * QSTR + c * 8) = *(const uint4*)(Klp + goff);
            *(uint4*)(sVh + r * QSTR + c * 8) = *(const uint4*)(Vhp + goff);
            *(uint4*)(sVl + r * QSTR + c * 8) = *(const uint4*)(Vlp + goff);
        }
        __syncthreads();

        // ---- scores: 16x64 per warp, split-bf16 (3 MMA terms) ----
        // K is k-major (rows=k_idx, cols=d) => B operand uses NON-trans ldmatrix
        // (fragment holds K[n=lane/4][k=2*(lane%4)+i], exactly the col-major B map).
        float c[8][4];
#pragma unroll
        for (int j = 0; j < 8; j++) {
            u32 bh[4], bl[4];
            u32 base = (j * 8 + (lane & 7)) * QSTR + ((lane >> 3) & 3) * 8;
            ldsm_x4(bh[0], bh[1], bh[2], bh[3], s2u(&sKh[base]));
            ldsm_x4(bl[0], bl[1], bl[2], bl[3], s2u(&sKl[base]));
            c[j][0] = c[j][1] = c[j][2] = c[j][3] = 0.0f;
            mma_bf16(c[j], qa_h[0], bh[0], bh[1]);
            mma_bf16(c[j], qa_h[1], bh[2], bh[3]);
            mma_bf16(c[j], qa_h[0], bl[0], bl[1]);
            mma_bf16(c[j], qa_h[1], bl[2], bl[3]);
            mma_bf16(c[j], qa_l[0], bh[0], bh[1]);
            mma_bf16(c[j], qa_l[1], bh[2], bh[3]);
        }

        // ---- mask + exp + rowsum + Es + pack E into A-fragments ----
        u32 eh[4][4], el[4][4];
#pragma unroll
        for (int j = 0; j < 8; j++) {
            int kk = j * 8 + tig * 2;
            uchar2 m0 = *(const uchar2*)(mbase0 + kc0 + kk);
            uchar2 m1 = *(const uchar2*)(mbase1 + kc0 + kk);
            float e0 = m0.x ? 0.0f : __expf(c[j][0]);
            float e1 = m0.y ? 0.0f : __expf(c[j][1]);
            float e2 = m1.x ? 0.0f : __expf(c[j][2]);
            float e3 = m1.y ? 0.0f : __expf(c[j][3]);
            rs0 += e0 + e1;
            rs1 += e2 + e3;
            *(float2*)(sEs + (w * 16 + g) * ESTR + kk) = make_float2(e0, e1);
            *(float2*)(sEs + (w * 16 + g + 8) * ESTR + kk) = make_float2(e2, e3);
            float h0 = __bfloat162float(__float2bfloat16_rn(e0));
            float h1 = __bfloat162float(__float2bfloat16_rn(e1));
            float h2 = __bfloat162float(__float2bfloat16_rn(e2));
            float h3 = __bfloat162float(__float2bfloat16_rn(e3));
            int kc2 = j >> 1, off = (j & 1) * 2;
            eh[kc2][off + 0] = bpack(h0, h1);
            eh[kc2][off + 1] = bpack(h2, h3);
            el[kc2][off + 0] = bpack(e0 - h0, e1 - h1);
            el[kc2][off + 1] = bpack(e2 - h2, e3 - h3);
        }

        // ---- context: ctx += Ehi*Vhi + Ehi*Vlo + Elo*Vhi ----
        // V is k-major but MMA k runs over V rows => trans ldmatrix is correct here.
#pragma unroll
        for (int jd = 0; jd < 4; jd++) {
            u32 vh[8], vl[8];
            ldsm_x4t(vh[0], vh[1], vh[2], vh[3], s2u(&sVh[lane * QSTR + jd * 8]));
            ldsm_x4t(vh[4], vh[5], vh[6], vh[7], s2u(&sVh[(32 + lane) * QSTR + jd * 8]));
            ldsm_x4t(vl[0], vl[1], vl[2], vl[3], s2u(&sVl[lane * QSTR + jd * 8]));
            ldsm_x4t(vl[4], vl[5], vl[6], vl[7], s2u(&sVl[(32 + lane) * QSTR + jd * 8]));
#pragma unroll
            for (int kc2 = 0; kc2 < 4; kc2++) {
                mma_bf16(oc[jd], eh[kc2], vh[kc2 * 2], vh[kc2 * 2 + 1]);
                mma_bf16(oc[jd], eh[kc2], vl[kc2 * 2], vl[kc2 * 2 + 1]);
                mma_bf16(oc[jd], el[kc2], vh[kc2 * 2], vh[kc2 * 2 + 1]);
            }
        }
        __syncthreads();

        // ---- Es -> gmem (unnormalized attn) ----
        if (attn_out) {
            for (int i = tid; i < 128 * 16; i += 256) {
                int r = i >> 4, c4 = i & 15;
                ((float4*)(attn_out + ((size_t)h * SEQ + qb + r) * SEQ + kc0))[c4] =
                    *(float4*)(sEs + r * ESTR + c4 * 4);
            }
        }
    }

    // ---- rowsums ----
    float r0 = rs0;
    r0 += __shfl_xor_sync(0xFFFFFFFFu, r0, 1);
    r0 += __shfl_xor_sync(0xFFFFFFFFu, r0, 2);
    float r1 = rs1;
    r1 += __shfl_xor_sync(0xFFFFFFFFu, r1, 1);
    r1 += __shfl_xor_sync(0xFFFFFFFFu, r1, 2);
    if (tig == 0) {
        g_rowsum[h * SEQ + q0] = r0;
        g_rowsum[h * SEQ + q0 + 8] = r1;
    }

    // ---- context writeout (unnormalized) ----
#pragma unroll
    for (int jd = 0; jd < 4; jd++) {
        float* d0 = g_ctx + (size_t)q0 * DM + h * HD + jd * 8 + tig * 2;
        *(float2*)d0 = make_float2(oc[jd][0], oc[jd][1]);
        float* d1 = d0 + (size_t)8 * DM;
        *(float2*)d1 = make_float2(oc[jd][2], oc[jd][3]);
    }
}

// ---------------- invert row sums ----------------
__global__ void rinv_kernel() {
    int i = blockIdx.x * 256 + threadIdx.x;
    if (i < NH * SEQ) g_rowsum[i] = 1.0f / g_rowsum[i];
}

// ---------------- normalize attn rows in place ----------------
__global__ __launch_bounds__(256) void norm_attn_kernel(float* __restrict__ attn) {
    int row = blockIdx.x;  // h*SEQ + q
    float inv = g_rowsum[row];
    float4* p = (float4*)(attn + (size_t)row * SEQ);
    for (int i = threadIdx.x; i < SEQ / 4; i += 256) {
        float4 v = p[i];
        v.x *= inv; v.y *= inv; v.z *= inv; v.w *= inv;
        p[i] = v;
    }
}

// ---------------- output projection: g_fc = (ctx * inv_sum) @ W_fc^T ----------------
__global__ __launch_bounds__(256) void fc_kernel(const float* __restrict__ W) {
    __shared__ float Xs[16][68];
    __shared__ float Ws[16][68];
    int bm = blockIdx.y * 64, bn = blockIdx.x * 64;
    int tid = threadIdx.x;
    int tx = (tid & 15) * 4, ty = (tid >> 4) * 4;
    float acc[4][4] = {};
    for (int k0 = 0; k0 < DM; k0 += 16) {
        for (int i = tid; i < 1024; i += 256) {
            int r = i >> 4, kk = i & 15;
            int c = k0 + kk;
            Xs[kk][r] = g_ctx[(size_t)(bm + r) * DM + c] * g_rowsum[(c >> 5) * SEQ + bm + r];
            Ws[kk][r] = W[(size_t)(bn + r) * DM + c];
        }
        __syncthreads();
#pragma unroll
        for (int kk = 0; kk < 16; kk++) {
            float xv[4], wv[4];
#pragma unroll
            for (int i = 0; i < 4; i++) xv[i] = Xs[kk][ty + i];
#pragma unroll
            for (int j = 0; j < 4; j++) wv[j] = Ws[kk][tx + j];
#pragma unroll
            for (int i = 0; i < 4; i++)
#pragma unroll
                for (int j = 0; j < 4; j++) acc[i][j] += xv[i] * wv[j];
        }
        __syncthreads();
    }
#pragma unroll
    for (int i = 0; i < 4; i++)
#pragma unroll
        for (int j = 0; j < 4; j++)
            g_fc[(size_t)(bm + ty + i) * DM + bn + tx + j] = acc[i][j];
}

// ---------------- LayerNorm ----------------
__global__ __launch_bounds__(256) void ln_kernel(const float* __restrict__ lnw,
                                                 const float* __restrict__ lnb,
                                                 float* __restrict__ out) {
    int n = blockIdx.x, t = threadIdx.x, lane = t & 31, w = t >> 5;
    __shared__ float red[8];
    float x = g_fc[(size_t)n * DM + t];
    float s = x;
#pragma unroll
    for (int o = 16; o; o >>= 1) s += __shfl_xor_sync(0xFFFFFFFFu, s, o);
    if (lane == 0) red[w] = s;
    __syncthreads();
    float mu = 0;
#pragma unroll
    for (int i = 0; i < 8; i++) mu += red[i];
    mu *= (1.0f / DM);
    __syncthreads();
    float d = x - mu;
    float s2 = d * d;
#pragma unroll
    for (int o = 16; o; o >>= 1) s2 += __shfl_xor_sync(0xFFFFFFFFu, s2, o);
    if (lane == 0) red[w] = s2;
    __syncthreads();
    float var = 0;
#pragma unroll
    for (int i = 0; i < 8; i++) var += red[i];
    var *= (1.0f / DM);
    out[(size_t)n * DM + t] = d * rsqrtf(var + 1e-5f) * lnw[t] + lnb[t];
}

// ---------------- launch ----------------
extern "C" void kernel_launch(void* const* d_in, const int* in_sizes, int n_in,
                              void* d_out, int out_size) {
    const float* iQ = (const float*)d_in[0];
    const float* iK = (const float*)d_in[1];
    const float* iV = (const float*)d_in[2];
    const void* mask = d_in[3];
    const float* WQ = (const float*)d_in[4];
    const float* WK = (const float*)d_in[5];
    const float* WV = (const float*)d_in[6];
    const float* Wfc = (const float*)d_in[7];
    const float* lnw = (const float*)d_in[8];
    const float* lnb = (const float*)d_in[9];
    float* out = (float*)d_out;

    long long attn_elems = (long long)NH * SEQ * SEQ;
    long long attn_off = (long long)out_size - attn_elems;
    float* attn_out = (attn_off >= 0) ? (out + attn_off) : nullptr;

    cudaFuncSetAttribute(attn_kernel, cudaFuncAttributeMaxDynamicSharedMemorySize, ATTN_SMEM);

    detect_mask_kernel<<<1, 32>>>(mask);
    conv_mask_kernel<<<4096, 256>>>(mask);
    proj_kernel<<<dim3(4, 64, 3), 256>>>(iQ, iK, iV, WQ, WK, WV);
    attn_kernel<<<dim3(32, 8), 256, ATTN_SMEM>>>(attn_out);
    rinv_kernel<<<(NH * SEQ + 255) / 256, 256>>>();
    if (attn_out) norm_attn_kernel<<<NH * SEQ, 256>>>(attn_out);
    fc_kernel<<<dim3(4, 64), 256>>>(Wfc);
    ln_kernel<<<SEQ, 256>>>(lnw, lnb, out);
}

// round 7
// speedup vs baseline: 2.3107x; 1.1033x over previous
#include <cuda_runtime.h>
#include <cuda_bf16.h>
#include <math.h>

#define SEQ 4096
#define NH 8
#define HD 32
#define DM 256
#define IN_F 256

typedef unsigned int u32;

// ---------------- scratch (static device globals; no allocation) ----------------
__device__ __nv_bfloat16 g_Qh[NH * SEQ * HD];  // bf16 hi part, Q pre-scaled by 1/sqrt(32)
__device__ __nv_bfloat16 g_Ql[NH * SEQ * HD];  // bf16 residual
__device__ __nv_bfloat16 g_Kh[NH * SEQ * HD];
__device__ __nv_bfloat16 g_Kl[NH * SEQ * HD];
__device__ __nv_bfloat16 g_Vh[NH * SEQ * HD];
__device__ __nv_bfloat16 g_Vl[NH * SEQ * HD];
__device__ float g_ctx[SEQ * DM];              // normalized context
__device__ float g_fc[SEQ * DM];
__device__ unsigned char g_mask[(size_t)SEQ * SEQ];
__device__ int g_mask_mode;

// ---------------- mask dtype detection + canonicalization ----------------
__global__ void detect_mask_kernel(const void* m) {
    const unsigned int* p = (const unsigned int*)m;
    int lane = threadIdx.x;
    int isint = 1, isfloat = 1;
    for (int i = lane; i < 256; i += 32) {
        unsigned int v = p[i];
        if (v > 1u) isint = 0;
        if (v != 0u && v != 0x3F800000u) isfloat = 0;
    }
    isint = __all_sync(0xFFFFFFFFu, isint);
    isfloat = __all_sync(0xFFFFFFFFu, isfloat);
    if (lane == 0) g_mask_mode = isint ? 1 : (isfloat ? 2 : 0);
}

__global__ void conv_mask_kernel(const void* m) {
    int mode = g_mask_mode;
    size_t idx = (size_t)blockIdx.x * blockDim.x + threadIdx.x;
    size_t stride = (size_t)gridDim.x * blockDim.x;
    size_t total = (size_t)SEQ * SEQ;
    if (mode == 1) {
        const int* p = (const int*)m;
        for (size_t i = idx; i < total; i += stride) g_mask[i] = (p[i] != 0);
    } else if (mode == 2) {
        const float* p = (const float*)m;
        for (size_t i = idx; i < total; i += stride) g_mask[i] = (p[i] != 0.0f);
    } else {
        const unsigned char* p = (const unsigned char*)m;
        for (size_t i = idx; i < total; i += stride) g_mask[i] = (p[i] != 0);
    }
}

// ---------------- input projections: Y = X @ W^T -> bf16 hi/lo, split heads ----------------
__global__ __launch_bounds__(256) void proj_kernel(const float* __restrict__ XQ,
                                                   const float* __restrict__ XK,
                                                   const float* __restrict__ XV,
                                                   const float* __restrict__ WQ,
                                                   const float* __restrict__ WK,
                                                   const float* __restrict__ WV) {
    int which = blockIdx.z;
    const float* X = (which == 0) ? XQ : (which == 1) ? XK : XV;
    const float* W = (which == 0) ? WQ : (which == 1) ? WK : WV;
    __nv_bfloat16* oh = (which == 0) ? g_Qh : (which == 1) ? g_Kh : g_Vh;
    __nv_bfloat16* ol = (which == 0) ? g_Ql : (which == 1) ? g_Kl : g_Vl;
    float scale = (which == 0) ? 0.17677669529663687f : 1.0f;  // 1/sqrt(32) into Q
    __shared__ float Xs[16][68];
    __shared__ float Ws[16][68];
    int bm = blockIdx.y * 64, bn = blockIdx.x * 64;
    int tid = threadIdx.x;
    int tx = (tid & 15) * 4, ty = (tid >> 4) * 4;
    float acc[4][4] = {};
    for (int k0 = 0; k0 < IN_F; k0 += 16) {
        for (int i = tid; i < 1024; i += 256) {
            int r = i >> 4, kk = i & 15;
            Xs[kk][r] = X[(size_t)(bm + r) * IN_F + k0 + kk];
            Ws[kk][r] = W[(size_t)(bn + r) * IN_F + k0 + kk];
        }
        __syncthreads();
#pragma unroll
        for (int kk = 0; kk < 16; kk++) {
            float xv[4], wv[4];
#pragma unroll
            for (int i = 0; i < 4; i++) xv[i] = Xs[kk][ty + i];
#pragma unroll
            for (int j = 0; j < 4; j++) wv[j] = Ws[kk][tx + j];
#pragma unroll
            for (int i = 0; i < 4; i++)
#pragma unroll
                for (int j = 0; j < 4; j++) acc[i][j] += xv[i] * wv[j];
        }
        __syncthreads();
    }
#pragma unroll
    for (int i = 0; i < 4; i++) {
        int m = bm + ty + i;
#pragma unroll
        for (int j = 0; j < 4; j++) {
            int o = bn + tx + j;
            float v = acc[i][j] * scale;
            __nv_bfloat16 hi = __float2bfloat16_rn(v);
            float lo = v - __bfloat162float(hi);
            size_t dst = (size_t)(o >> 5) * (SEQ * HD) + (size_t)m * HD + (o & 31);
            oh[dst] = hi;
            ol[dst] = __float2bfloat16_rn(lo);
        }
    }
}

// ---------------- tensor-core attention (2-pass recompute, no normalize kernel) ----------------
#define QSTR 40  // bf16 row stride for Q/K/V smem tiles
#define ATTN_SMEM ((128 * 2 + 64 * 4) * QSTR * 2)  // 40960 B

__device__ __forceinline__ u32 s2u(const void* p) { return (u32)__cvta_generic_to_shared(p); }

__device__ __forceinline__ void ldsm_x4(u32& r0, u32& r1, u32& r2, u32& r3, u32 addr) {
    asm volatile("ldmatrix.sync.aligned.m8n8.x4.shared.b16 {%0,%1,%2,%3}, [%4];"
                 : "=r"(r0), "=r"(r1), "=r"(r2), "=r"(r3) : "r"(addr));
}
__device__ __forceinline__ void ldsm_x4t(u32& r0, u32& r1, u32& r2, u32& r3, u32 addr) {
    asm volatile("ldmatrix.sync.aligned.m8n8.x4.trans.shared.b16 {%0,%1,%2,%3}, [%4];"
                 : "=r"(r0), "=r"(r1), "=r"(r2), "=r"(r3) : "r"(addr));
}
__device__ __forceinline__ void mma_bf16(float* c, const u32* a, u32 b0, u32 b1) {
    asm volatile(
        "mma.sync.aligned.m16n8k16.row.col.f32.bf16.bf16.f32 "
        "{%0,%1,%2,%3}, {%4,%5,%6,%7}, {%8,%9}, {%0,%1,%2,%3};"
        : "+f"(c[0]), "+f"(c[1]), "+f"(c[2]), "+f"(c[3])
        : "r"(a[0]), "r"(a[1]), "r"(a[2]), "r"(a[3]), "r"(b0), "r"(b1));
}
__device__ __forceinline__ u32 bpack(float lo, float hi) {
    u32 r;
    asm("cvt.rn.bf16x2.f32 %0, %1, %2;" : "=r"(r) : "f"(hi), "f"(lo));
    return r;
}

__global__ __launch_bounds__(256, 2) void attn_kernel(float* __restrict__ attn_out) {
    extern __shared__ char smem_raw[];
    __nv_bfloat16* sQh = (__nv_bfloat16*)smem_raw;
    __nv_bfloat16* sQl = sQh + 128 * QSTR;
    __nv_bfloat16* sKh = sQl + 128 * QSTR;
    __nv_bfloat16* sKl = sKh + 64 * QSTR;
    __nv_bfloat16* sVh = sKl + 64 * QSTR;
    __nv_bfloat16* sVl = sVh + 64 * QSTR;

    int h = blockIdx.y;
    int qb = blockIdx.x * 128;
    int tid = threadIdx.x, w = tid >> 5, lane = tid & 31;
    int g = lane >> 2, tig = lane & 3;

    // load Q tile (128x32 hi/lo) into smem
    {
        const uint4* srch = (const uint4*)(g_Qh + ((size_t)h * SEQ + qb) * HD);
        const uint4* srcl = (const uint4*)(g_Ql + ((size_t)h * SEQ + qb) * HD);
        for (int i = tid; i < 128 * 4; i += 256) {
            int r = i >> 2, c = i & 3;
            *(uint4*)(sQh + r * QSTR + c * 8) = srch[r * 4 + c];
            *(uint4*)(sQl + r * QSTR + c * 8) = srcl[r * 4 + c];
        }
    }
    __syncthreads();

    // Q fragments (held in registers for the whole kernel)
    u32 qa_h[2][4], qa_l[2][4];
    {
        int row = w * 16 + (lane & 15);
        int colb = ((lane >> 4) & 1) * 8;
#pragma unroll
        for (int kc = 0; kc < 2; kc++) {
            ldsm_x4(qa_h[kc][0], qa_h[kc][1], qa_h[kc][2], qa_h[kc][3],
                    s2u(&sQh[row * QSTR + kc * 16 + colb]));
            ldsm_x4(qa_l[kc][0], qa_l[kc][1], qa_l[kc][2], qa_l[kc][3],
                    s2u(&sQl[row * QSTR + kc * 16 + colb]));
        }
    }

    const __nv_bfloat16* Khp = g_Kh + (size_t)h * SEQ * HD;
    const __nv_bfloat16* Klp = g_Kl + (size_t)h * SEQ * HD;
    const __nv_bfloat16* Vhp = g_Vh + (size_t)h * SEQ * HD;
    const __nv_bfloat16* Vlp = g_Vl + (size_t)h * SEQ * HD;

    int q0 = qb + w * 16 + g;
    const unsigned char* mbase0 = g_mask + (size_t)q0 * SEQ;
    const unsigned char* mbase1 = mbase0 + (size_t)8 * SEQ;

    int ldr = tid >> 2, ldc = tid & 3;  // K/V cooperative-load coords (64 rows x 4 chunks)

    // ================= PASS A: rowsums (hi-only scores) =================
    float rs0 = 0.0f, rs1 = 0.0f;
    for (int kc0 = 0; kc0 < SEQ; kc0 += 64) {
        __syncthreads();
        *(uint4*)(sKh + ldr * QSTR + ldc * 8) =
            *(const uint4*)(Khp + (size_t)(kc0 + ldr) * HD + ldc * 8);
        __syncthreads();
        // prefetch masks
        uchar2 pm0[8], pm1[8];
#pragma unroll
        for (int j = 0; j < 8; j++) {
            int kk = j * 8 + tig * 2;
            pm0[j] = *(const uchar2*)(mbase0 + kc0 + kk);
            pm1[j] = *(const uchar2*)(mbase1 + kc0 + kk);
        }
#pragma unroll
        for (int j = 0; j < 8; j++) {
            u32 bh[4];
            u32 base = (j * 8 + (lane & 7)) * QSTR + ((lane >> 3) & 3) * 8;
            ldsm_x4(bh[0], bh[1], bh[2], bh[3], s2u(&sKh[base]));
            float c[4] = {0, 0, 0, 0};
            mma_bf16(c, qa_h[0], bh[0], bh[1]);
            mma_bf16(c, qa_h[1], bh[2], bh[3]);
            rs0 += (pm0[j].x ? 0.0f : __expf(c[0])) + (pm0[j].y ? 0.0f : __expf(c[1]));
            rs1 += (pm1[j].x ? 0.0f : __expf(c[2])) + (pm1[j].y ? 0.0f : __expf(c[3]));
        }
    }
    // quad-reduce rowsums -> inverses (all 4 lanes of the quad get the value)
    rs0 += __shfl_xor_sync(0xFFFFFFFFu, rs0, 1);
    rs0 += __shfl_xor_sync(0xFFFFFFFFu, rs0, 2);
    rs1 += __shfl_xor_sync(0xFFFFFFFFu, rs1, 1);
    rs1 += __shfl_xor_sync(0xFFFFFFFFu, rs1, 2);
    float inv0 = 1.0f / rs0;
    float inv1 = 1.0f / rs1;

    // ================= PASS B: normalized attn + context =================
    float oc[4][4] = {};  // context accumulators [d8-tile][frag]
    float* arow0 = attn_out ? (attn_out + ((size_t)h * SEQ + q0) * SEQ) : nullptr;
    float* arow1 = arow0 ? (arow0 + (size_t)8 * SEQ) : nullptr;

    for (int kc0 = 0; kc0 < SEQ; kc0 += 64) {
        __syncthreads();
        {
            size_t goff = (size_t)(kc0 + ldr) * HD + ldc * 8;
            *(uint4*)(sKh + ldr * QSTR + ldc * 8) = *(const uint4*)(Khp + goff);
            *(uint4*)(sKl + ldr * QSTR + ldc * 8) = *(const uint4*)(Klp + goff);
            *(uint4*)(sVh + ldr * QSTR + ldc * 8) = *(const uint4*)(Vhp + goff);
            *(uint4*)(sVl + ldr * QSTR + ldc * 8) = *(const uint4*)(Vlp + goff);
        }
        __syncthreads();
        uchar2 pm0[8], pm1[8];
#pragma unroll
        for (int j = 0; j < 8; j++) {
            int kk = j * 8 + tig * 2;
            pm0[j] = *(const uchar2*)(mbase0 + kc0 + kk);
            pm1[j] = *(const uchar2*)(mbase1 + kc0 + kk);
        }
        u32 eh[4][4], el[4][4];
#pragma unroll
        for (int j = 0; j < 8; j++) {
            u32 bh[4], bl[4];
            u32 base = (j * 8 + (lane & 7)) * QSTR + ((lane >> 3) & 3) * 8;
            ldsm_x4(bh[0], bh[1], bh[2], bh[3], s2u(&sKh[base]));
            ldsm_x4(bl[0], bl[1], bl[2], bl[3], s2u(&sKl[base]));
            float c[4] = {0, 0, 0, 0};
            mma_bf16(c, qa_h[0], bh[0], bh[1]);
            mma_bf16(c, qa_h[1], bh[2], bh[3]);
            mma_bf16(c, qa_h[0], bl[0], bl[1]);
            mma_bf16(c, qa_h[1], bl[2], bl[3]);
            mma_bf16(c, qa_l[0], bh[0], bh[1]);
            mma_bf16(c, qa_l[1], bh[2], bh[3]);
            // normalized probabilities
            float e0 = pm0[j].x ? 0.0f : __expf(c[0]) * inv0;
            float e1 = pm0[j].y ? 0.0f : __expf(c[1]) * inv0;
            float e2 = pm1[j].x ? 0.0f : __expf(c[2]) * inv1;
            float e3 = pm1[j].y ? 0.0f : __expf(c[3]) * inv1;
            int kk = j * 8 + tig * 2;
            if (arow0) {
                *(float2*)(arow0 + kc0 + kk) = make_float2(e0, e1);
                *(float2*)(arow1 + kc0 + kk) = make_float2(e2, e3);
            }
            float h0 = __bfloat162float(__float2bfloat16_rn(e0));
            float h1 = __bfloat162float(__float2bfloat16_rn(e1));
            float h2 = __bfloat162float(__float2bfloat16_rn(e2));
            float h3 = __bfloat162float(__float2bfloat16_rn(e3));
            int kc2 = j >> 1, off = (j & 1) * 2;
            eh[kc2][off + 0] = bpack(h0, h1);
            eh[kc2][off + 1] = bpack(h2, h3);
            el[kc2][off + 0] = bpack(e0 - h0, e1 - h1);
            el[kc2][off + 1] = bpack(e2 - h2, e3 - h3);
        }
        // ---- context: ctx += Ehi*Vhi + Ehi*Vlo + Elo*Vhi ----
#pragma unroll
        for (int jd = 0; jd < 4; jd++) {
            u32 vh[8], vl[8];
            ldsm_x4t(vh[0], vh[1], vh[2], vh[3], s2u(&sVh[lane * QSTR + jd * 8]));
            ldsm_x4t(vh[4], vh[5], vh[6], vh[7], s2u(&sVh[(32 + lane) * QSTR + jd * 8]));
            ldsm_x4t(vl[0], vl[1], vl[2], vl[3], s2u(&sVl[lane * QSTR + jd * 8]));
            ldsm_x4t(vl[4], vl[5], vl[6], vl[7], s2u(&sVl[(32 + lane) * QSTR + jd * 8]));
#pragma unroll
            for (int kc2 = 0; kc2 < 4; kc2++) {
                mma_bf16(oc[jd], eh[kc2], vh[kc2 * 2], vh[kc2 * 2 + 1]);
                mma_bf16(oc[jd], eh[kc2], vl[kc2 * 2], vl[kc2 * 2 + 1]);
                mma_bf16(oc[jd], el[kc2], vh[kc2 * 2], vh[kc2 * 2 + 1]);
            }
        }
    }

    // ---- context writeout (already normalized) ----
#pragma unroll
    for (int jd = 0; jd < 4; jd++) {
        float* d0 = g_ctx + (size_t)q0 * DM + h * HD + jd * 8 + tig * 2;
        *(float2*)d0 = make_float2(oc[jd][0], oc[jd][1]);
        float* d1 = d0 + (size_t)8 * DM;
        *(float2*)d1 = make_float2(oc[jd][2], oc[jd][3]);
    }
}

// ---------------- output projection: g_fc = ctx @ W_fc^T ----------------
__global__ __launch_bounds__(256) void fc_kernel(const float* __restrict__ W) {
    __shared__ float Xs[16][68];
    __shared__ float Ws[16][68];
    int bm = blockIdx.y * 64, bn = blockIdx.x * 64;
    int tid = threadIdx.x;
    int tx = (tid & 15) * 4, ty = (tid >> 4) * 4;
    float acc[4][4] = {};
    for (int k0 = 0; k0 < DM; k0 += 16) {
        for (int i = tid; i < 1024; i += 256) {
            int r = i >> 4, kk = i & 15;
            int c = k0 + kk;
            Xs[kk][r] = g_ctx[(size_t)(bm + r) * DM + c];
            Ws[kk][r] = W[(size_t)(bn + r) * DM + c];
        }
        __syncthreads();
#pragma unroll
        for (int kk = 0; kk < 16; kk++) {
            float xv[4], wv[4];
#pragma unroll
            for (int i = 0; i < 4; i++) xv[i] = Xs[kk][ty + i];
#pragma unroll
            for (int j = 0; j < 4; j++) wv[j] = Ws[kk][tx + j];
#pragma unroll
            for (int i = 0; i < 4; i++)
#pragma unroll
                for (int j = 0; j < 4; j++) acc[i][j] += xv[i] * wv[j];
        }
        __syncthreads();
    }
#pragma unroll
    for (int i = 0; i < 4; i++)
#pragma unroll
        for (int j = 0; j < 4; j++)
            g_fc[(size_t)(bm + ty + i) * DM + bn + tx + j] = acc[i][j];
}

// ---------------- LayerNorm ----------------
__global__ __launch_bounds__(256) void ln_kernel(const float* __restrict__ lnw,
                                                 const float* __restrict__ lnb,
                                                 float* __restrict__ out) {
    int n = blockIdx.x, t = threadIdx.x, lane = t & 31, w = t >> 5;
    __shared__ float red[8];
    float x = g_fc[(size_t)n * DM + t];
    float s = x;
#pragma unroll
    for (int o = 16; o; o >>= 1) s += __shfl_xor_sync(0xFFFFFFFFu, s, o);
    if (lane == 0) red[w] = s;
    __syncthreads();
    float mu = 0;
#pragma unroll
    for (int i = 0; i < 8; i++) mu += red[i];
    mu *= (1.0f / DM);
    __syncthreads();
    float d = x - mu;
    float s2 = d * d;
#pragma unroll
    for (int o = 16; o; o >>= 1) s2 += __shfl_xor_sync(0xFFFFFFFFu, s2, o);
    if (lane == 0) red[w] = s2;
    __syncthreads();
    float var = 0;
#pragma unroll
    for (int i = 0; i < 8; i++) var += red[i];
    var *= (1.0f / DM);
    out[(size_t)n * DM + t] = d * rsqrtf(var + 1e-5f) * lnw[t] + lnb[t];
}

// ---------------- launch ----------------
extern "C" void kernel_launch(void* const* d_in, const int* in_sizes, int n_in,
                              void* d_out, int out_size) {
    const float* iQ = (const float*)d_in[0];
    const float* iK = (const float*)d_in[1];
    const float* iV = (const float*)d_in[2];
    const void* mask = d_in[3];
    const float* WQ = (const float*)d_in[4];
    const float* WK = (const float*)d_in[5];
    const float* WV = (const float*)d_in[6];
    const float* Wfc = (const float*)d_in[7];
    const float* lnw = (const float*)d_in[8];
    const float* lnb = (const float*)d_in[9];
    float* out = (float*)d_out;

    long long attn_elems = (long long)NH * SEQ * SEQ;
    long long attn_off = (long long)out_size - attn_elems;
    float* attn_out = (attn_off >= 0) ? (out + attn_off) : nullptr;

    cudaFuncSetAttribute(attn_kernel, cudaFuncAttributeMaxDynamicSharedMemorySize, ATTN_SMEM);

    detect_mask_kernel<<<1, 32>>>(mask);
    conv_mask_kernel<<<4096, 256>>>(mask);
    proj_kernel<<<dim3(4, 64, 3), 256>>>(iQ, iK, iV, WQ, WK, WV);
    attn_kernel<<<dim3(32, 8), 256, ATTN_SMEM>>>(attn_out);
    fc_kernel<<<dim3(4, 64), 256>>>(Wfc);
    ln_kernel<<<SEQ, 256>>>(lnw, lnb, out);
}